// round 3
// baseline (speedup 1.0000x reference)
#include <cuda_runtime.h>
#include <math.h>

// Problem constants
#define BATCH    64
#define IN_CAPS  2048
#define IN_DIM   8
#define NC       32
#define OUT_DIM  16
#define IB       8                       // input capsules per CTA
#define NIB      (IN_CAPS / IB)          // 256 i-blocks
#define BTILE    16
#define NBT      (BATCH / BTILE)         // 4
#define NV       (BATCH * NC * OUT_DIM)  // 32768

typedef unsigned long long u64t;

__device__ __align__(16) float g_s[3][NV];
__device__ __align__(16) float g_v[2][NV];
__device__ float g_logits[(size_t)BATCH * IN_CAPS * NC];  // 16MB

// ---- packed f32x2 helpers (Blackwell FFMA2 — only reachable via PTX) ----
__device__ __forceinline__ u64t pk2(float lo, float hi) {
    u64t r; asm("mov.b64 %0,{%1,%2};" : "=l"(r) : "f"(lo), "f"(hi)); return r;
}
__device__ __forceinline__ void upk2(u64t v, float& lo, float& hi) {
    asm("mov.b64 {%0,%1},%2;" : "=f"(lo), "=f"(hi) : "l"(v));
}
__device__ __forceinline__ u64t fma2(u64t a, u64t b, u64t c) {
    u64t d; asm("fma.rn.f32x2 %0,%1,%2,%3;" : "=l"(d) : "l"(a), "l"(b), "l"(c)); return d;
}

__device__ __forceinline__ void cp_async16(void* smem_dst, const void* gmem_src) {
    unsigned saddr = (unsigned)__cvta_generic_to_shared(smem_dst);
    asm volatile("cp.async.cg.shared.global [%0],[%1],16;" :: "r"(saddr), "l"(gmem_src));
}
__device__ __forceinline__ void cp_commit() { asm volatile("cp.async.commit_group;"); }
__device__ __forceinline__ void cp_wait_all() { asm volatile("cp.async.wait_group 0;" ::: "memory"); }

__global__ void zero_kernel() {
    int idx = blockIdx.x * blockDim.x + threadIdx.x;
    if (idx < 3 * NV) ((float*)g_s)[idx] = 0.0f;
}

// P = routing pass (0,1,2). lane = capsule n; warp g owns 2 batch rows.
template <int P>
__global__ void __launch_bounds__(256)
pass_kernel(const float* __restrict__ x, const float* __restrict__ W) {
    // double-buffered W tile: 32 rows (n) x 128 floats, padded to 132 (33 float4)
    __shared__ float4 Wsm[2][32 * 33];

    const int tid = threadIdx.x;
    const int n   = tid & 31;
    const int g   = tid >> 5;
    const int bA  = blockIdx.y * BTILE + g * 2;
    const int bB  = bA + 1;
    const int i0  = blockIdx.x * IB;

    // staging indices for this thread's 4 cp.async chunks
    int nr[4], r4[4];
#pragma unroll
    for (int k = 0; k < 4; k++) {
        int idx4 = tid + 256 * k;
        nr[k] = idx4 >> 5;
        r4[k] = idx4 & 31;
    }

    u64t accA2[8], accB2[8];
#pragma unroll
    for (int q = 0; q < 8; q++) { accA2[q] = 0ull; accB2[q] = 0ull; }

    u64t vA2[8], vB2[8];
    if constexpr (P > 0) {
        const float4* va = (const float4*)&g_v[P - 1][(bA * NC + n) * OUT_DIM];
        const float4* vb = (const float4*)&g_v[P - 1][(bB * NC + n) * OUT_DIM];
#pragma unroll
        for (int q = 0; q < 4; q++) {
            float4 a = va[q], b = vb[q];
            vA2[2 * q] = pk2(a.x, a.y); vA2[2 * q + 1] = pk2(a.z, a.w);
            vB2[2 * q] = pk2(b.x, b.y); vB2[2 * q + 1] = pk2(b.z, b.w);
        }
    }

    // prologue: stage W[i0] into buffer 0
    {
        const float4* Wg = (const float4*)(W + (size_t)i0 * (NC * IN_DIM * OUT_DIM));
#pragma unroll
        for (int k = 0; k < 4; k++)
            cp_async16(&Wsm[0][nr[k] * 33 + r4[k]], &Wg[tid + 256 * k]);
        cp_commit();
    }

    for (int ii = 0; ii < IB; ii++) {
        const int i   = i0 + ii;
        const int cur = ii & 1;
        cp_wait_all();
        __syncthreads();
        if (ii + 1 < IB) {
            const float4* Wg = (const float4*)(W + (size_t)(i + 1) * (NC * IN_DIM * OUT_DIM));
#pragma unroll
            for (int k = 0; k < 4; k++)
                cp_async16(&Wsm[cur ^ 1][nr[k] * 33 + r4[k]], &Wg[tid + 256 * k]);
            cp_commit();
        }

        // x rows (same address across warp -> broadcast loads)
        const float4* xrA = (const float4*)(x + ((size_t)bA * IN_CAPS + i) * IN_DIM);
        const float4* xrB = (const float4*)(x + ((size_t)bB * IN_CAPS + i) * IN_DIM);
        float4 xa0 = __ldg(xrA), xa1 = __ldg(xrA + 1);
        float4 xb0 = __ldg(xrB), xb1 = __ldg(xrB + 1);
        float xsA[8] = {xa0.x, xa0.y, xa0.z, xa0.w, xa1.x, xa1.y, xa1.z, xa1.w};
        float xsB[8] = {xb0.x, xb0.y, xb0.z, xb0.w, xb1.x, xb1.y, xb1.z, xb1.w};

        const float* wrow = (const float*)&Wsm[cur][0] + n * 132;

        if constexpr (P == 0) {
            // c = 1/32 uniformly -> accumulate raw sums directly
#pragma unroll
            for (int d = 0; d < IN_DIM; d++) {
                u64t xa2 = pk2(xsA[d], xsA[d]);
                u64t xb2 = pk2(xsB[d], xsB[d]);
                const ulonglong2* w2 = (const ulonglong2*)(wrow + d * OUT_DIM);
#pragma unroll
                for (int q = 0; q < 4; q++) {
                    ulonglong2 w = w2[q];
                    accA2[2 * q]     = fma2(w.x, xa2, accA2[2 * q]);
                    accA2[2 * q + 1] = fma2(w.y, xa2, accA2[2 * q + 1]);
                    accB2[2 * q]     = fma2(w.x, xb2, accB2[2 * q]);
                    accB2[2 * q + 1] = fma2(w.y, xb2, accB2[2 * q + 1]);
                }
            }
        } else {
            u64t uA2[8], uB2[8];
#pragma unroll
            for (int q = 0; q < 8; q++) { uA2[q] = 0ull; uB2[q] = 0ull; }
#pragma unroll
            for (int d = 0; d < IN_DIM; d++) {
                u64t xa2 = pk2(xsA[d], xsA[d]);
                u64t xb2 = pk2(xsB[d], xsB[d]);
                const ulonglong2* w2 = (const ulonglong2*)(wrow + d * OUT_DIM);
#pragma unroll
                for (int q = 0; q < 4; q++) {
                    ulonglong2 w = w2[q];
                    uA2[2 * q]     = fma2(w.x, xa2, uA2[2 * q]);
                    uA2[2 * q + 1] = fma2(w.y, xa2, uA2[2 * q + 1]);
                    uB2[2 * q]     = fma2(w.x, xb2, uB2[2 * q]);
                    uB2[2 * q + 1] = fma2(w.y, xb2, uB2[2 * q + 1]);
                }
            }
            // routing logit l = u . v  (packed dot, horizontal add at end)
            u64t dA2 = 0ull, dB2 = 0ull;
#pragma unroll
            for (int q = 0; q < 8; q++) {
                dA2 = fma2(uA2[q], vA2[q], dA2);
                dB2 = fma2(uB2[q], vB2[q], dB2);
            }
            float a0, a1, b0, b1;
            upk2(dA2, a0, a1); upk2(dB2, b0, b1);
            float lA = a0 + a1, lB = b0 + b1;
            if constexpr (P == 2) {
                lA += g_logits[((size_t)bA * IN_CAPS + i) * NC + n];
                lB += g_logits[((size_t)bB * IN_CAPS + i) * NC + n];
            } else {
                g_logits[((size_t)bA * IN_CAPS + i) * NC + n] = lA;
                g_logits[((size_t)bB * IN_CAPS + i) * NC + n] = lB;
            }
            // softmax over the 32 capsules = full-warp reduce
            float mA = lA, mB = lB;
#pragma unroll
            for (int o = 16; o > 0; o >>= 1) {
                mA = fmaxf(mA, __shfl_xor_sync(0xffffffffu, mA, o));
                mB = fmaxf(mB, __shfl_xor_sync(0xffffffffu, mB, o));
            }
            float pA = __expf(lA - mA), pB = __expf(lB - mB);
            float ZA = pA, ZB = pB;
#pragma unroll
            for (int o = 16; o > 0; o >>= 1) {
                ZA += __shfl_xor_sync(0xffffffffu, ZA, o);
                ZB += __shfl_xor_sync(0xffffffffu, ZB, o);
            }
            u64t cA2 = pk2(pA / ZA, pA / ZA);
            u64t cB2 = pk2(pB / ZB, pB / ZB);
#pragma unroll
            for (int q = 0; q < 8; q++) {
                accA2[q] = fma2(uA2[q], cA2, accA2[q]);
                accB2[q] = fma2(uB2[q], cB2, accB2[q]);
            }
        }
    }

    // flush partial sums
    float* s = g_s[P];
#pragma unroll
    for (int q = 0; q < 8; q++) {
        float a0, a1, b0, b1;
        upk2(accA2[q], a0, a1); upk2(accB2[q], b0, b1);
        atomicAdd(&s[(bA * NC + n) * OUT_DIM + 2 * q], a0);
        atomicAdd(&s[(bA * NC + n) * OUT_DIM + 2 * q + 1], a1);
        atomicAdd(&s[(bB * NC + n) * OUT_DIM + 2 * q], b0);
        atomicAdd(&s[(bB * NC + n) * OUT_DIM + 2 * q + 1], b1);
    }
}

// squash(v) = (|v|^2/(1+|v|^2)/|v|) * v ; pass-0 1/32 scale folded in here
template <int K>
__global__ void squash_kernel(float* out_ext) {
    int idx = blockIdx.x * blockDim.x + threadIdx.x;
    if (idx >= BATCH * NC) return;
    const float scale = (K == 0) ? (1.0f / 32.0f) : 1.0f;
    const float* s = g_s[K];
    float* out;
    if constexpr (K == 2) out = out_ext; else out = g_v[K];

    float w[OUT_DIM];
    float s2 = 0.0f;
#pragma unroll
    for (int e = 0; e < OUT_DIM; e++) {
        w[e] = s[idx * OUT_DIM + e] * scale;
        s2 += w[e] * w[e];
    }
    float sc = s2 / ((1.0f + s2) * sqrtf(fmaxf(s2, 1e-30f)));
#pragma unroll
    for (int e = 0; e < OUT_DIM; e++) out[idx * OUT_DIM + e] = sc * w[e];
}

extern "C" void kernel_launch(void* const* d_in, const int* in_sizes, int n_in,
                              void* d_out, int out_size) {
    const float* x = (const float*)d_in[0];   // [64, 2048, 8]
    const float* W = (const float*)d_in[1];   // [2048, 32, 8, 16]
    float* out = (float*)d_out;               // [64, 32, 16]

    zero_kernel<<<(3 * NV + 255) / 256, 256>>>();

    dim3 grid(NIB, NBT);
    dim3 sgrid((BATCH * NC + 255) / 256);

    pass_kernel<0><<<grid, 256>>>(x, W);
    squash_kernel<0><<<sgrid, 256>>>(nullptr);

    pass_kernel<1><<<grid, 256>>>(x, W);
    squash_kernel<1><<<sgrid, 256>>>(nullptr);

    pass_kernel<2><<<grid, 256>>>(x, W);
    squash_kernel<2><<<sgrid, 256>>>(out);
}

// round 4
// speedup vs baseline: 1.6284x; 1.6284x over previous
#include <cuda_runtime.h>
#include <math.h>

// Problem constants
#define BATCH    64
#define IN_CAPS  2048
#define IN_DIM   8
#define NC       32
#define OUT_DIM  16
#define IBLK     32                      // input capsules per CTA
#define NIB      (IN_CAPS / IBLK)        // 64
#define BTILE    8                       // batch rows per CTA (4 warps x 2 rows)
#define NBT      (BATCH / BTILE)         // 8
#define NV       (BATCH * NC * OUT_DIM)  // 32768

typedef unsigned long long u64t;

// Scratch (static device globals — no allocation allowed)
__device__ __align__(16) float  g_s[3][NV];
__device__ __align__(16) float  g_v[2][NV];
__device__ float g_logits[(size_t)BATCH * IN_CAPS * NC];          // 16MB
// Transposed weights: W_t[i][d][e/4][n] as float4  (32MB, L2-resident)
__device__ __align__(16) float4 g_Wt4[(size_t)IN_CAPS * IN_DIM * 4 * NC];

// ---- packed f32x2 helpers (Blackwell FFMA2, PTX-only) ----
__device__ __forceinline__ u64t pk2(float lo, float hi) {
    u64t r; asm("mov.b64 %0,{%1,%2};" : "=l"(r) : "f"(lo), "f"(hi)); return r;
}
__device__ __forceinline__ void upk2(u64t v, float& lo, float& hi) {
    asm("mov.b64 {%0,%1},%2;" : "=f"(lo), "=f"(hi) : "l"(v));
}
__device__ __forceinline__ u64t fma2(u64t a, u64t b, u64t c) {
    u64t d; asm("fma.rn.f32x2 %0,%1,%2,%3;" : "=l"(d) : "l"(a), "l"(b), "l"(c)); return d;
}

__global__ void zero_kernel() {
    int idx = blockIdx.x * blockDim.x + threadIdx.x;
    if (idx < 3 * NV) ((float*)g_s)[idx] = 0.0f;
}

// W[i][n][d][e] (row-major) -> W_t[i][d*4+q][n] float4 (q = e/4)
// One CTA per input capsule i; smem-tiled so both phases are coalesced.
__global__ void __launch_bounds__(256)
transpose_W(const float4* __restrict__ W4) {
    __shared__ float4 t[32][33];
    const int i   = blockIdx.x;
    const int tid = threadIdx.x;
    const float4* src = W4 + (size_t)i * 1024;     // 1024 float4 per capsule
#pragma unroll
    for (int k = 0; k < 4; k++) {
        int idx = tid + 256 * k;                   // in-linear = n*32 + dq
        t[idx >> 5][idx & 31] = src[idx];
    }
    __syncthreads();
    float4* dst = g_Wt4 + (size_t)i * 1024;
#pragma unroll
    for (int k = 0; k < 4; k++) {
        int idx = tid + 256 * k;                   // out-linear = dq*32 + n
        dst[idx] = t[idx & 31][idx >> 5];
    }
}

// P = routing pass (0,1,2). lane = capsule n; warp g owns 2 batch rows.
// No shared memory, no barriers: W streamed per-lane through L1 (coalesced).
template <int P>
__global__ void __launch_bounds__(128, 4)
pass_kernel(const float* __restrict__ x) {
    const int tid = threadIdx.x;
    const int n   = tid & 31;
    const int g   = tid >> 5;                  // warp 0..3
    const int bA  = blockIdx.y * BTILE + g * 2;
    const int bB  = bA + 1;
    const int i0  = blockIdx.x * IBLK;

    u64t accA2[8], accB2[8];
#pragma unroll
    for (int q = 0; q < 8; q++) { accA2[q] = 0ull; accB2[q] = 0ull; }

    u64t vA2[8], vB2[8];
    if constexpr (P > 0) {
        const float4* va = (const float4*)&g_v[P - 1][(bA * NC + n) * OUT_DIM];
        const float4* vb = (const float4*)&g_v[P - 1][(bB * NC + n) * OUT_DIM];
#pragma unroll
        for (int q = 0; q < 4; q++) {
            float4 a = va[q], b = vb[q];
            vA2[2 * q] = pk2(a.x, a.y); vA2[2 * q + 1] = pk2(a.z, a.w);
            vB2[2 * q] = pk2(b.x, b.y); vB2[2 * q + 1] = pk2(b.z, b.w);
        }
    }

    for (int ii = 0; ii < IBLK; ii++) {
        const int i = i0 + ii;

        // x rows: same address warp-wide -> broadcast loads
        const float4* xrA = (const float4*)(x + ((size_t)bA * IN_CAPS + i) * IN_DIM);
        const float4* xrB = (const float4*)(x + ((size_t)bB * IN_CAPS + i) * IN_DIM);
        float4 xa0 = __ldg(xrA), xa1 = __ldg(xrA + 1);
        float4 xb0 = __ldg(xrB), xb1 = __ldg(xrB + 1);
        float xsA[8] = {xa0.x, xa0.y, xa0.z, xa0.w, xa1.x, xa1.y, xa1.z, xa1.w};
        float xsB[8] = {xb0.x, xb0.y, xb0.z, xb0.w, xb1.x, xb1.y, xb1.z, xb1.w};

        const float4* wp = g_Wt4 + (size_t)i * 1024 + n;   // + (d*4+q)*32 per term

        if constexpr (P == 0) {
            // c = 1/32 uniformly (softmax of zeros): accumulate raw sums
#pragma unroll
            for (int d = 0; d < IN_DIM; d++) {
                u64t xa2 = pk2(xsA[d], xsA[d]);
                u64t xb2 = pk2(xsB[d], xsB[d]);
#pragma unroll
                for (int q = 0; q < 4; q++) {
                    float4 w = __ldg(wp + (d * 4 + q) * 32);
                    u64t w01 = pk2(w.x, w.y), w23 = pk2(w.z, w.w);
                    accA2[2 * q]     = fma2(w01, xa2, accA2[2 * q]);
                    accA2[2 * q + 1] = fma2(w23, xa2, accA2[2 * q + 1]);
                    accB2[2 * q]     = fma2(w01, xb2, accB2[2 * q]);
                    accB2[2 * q + 1] = fma2(w23, xb2, accB2[2 * q + 1]);
                }
            }
        } else {
            u64t uA2[8], uB2[8];
#pragma unroll
            for (int q = 0; q < 8; q++) { uA2[q] = 0ull; uB2[q] = 0ull; }
#pragma unroll
            for (int d = 0; d < IN_DIM; d++) {
                u64t xa2 = pk2(xsA[d], xsA[d]);
                u64t xb2 = pk2(xsB[d], xsB[d]);
#pragma unroll
                for (int q = 0; q < 4; q++) {
                    float4 w = __ldg(wp + (d * 4 + q) * 32);
                    u64t w01 = pk2(w.x, w.y), w23 = pk2(w.z, w.w);
                    uA2[2 * q]     = fma2(w01, xa2, uA2[2 * q]);
                    uA2[2 * q + 1] = fma2(w23, xa2, uA2[2 * q + 1]);
                    uB2[2 * q]     = fma2(w01, xb2, uB2[2 * q]);
                    uB2[2 * q + 1] = fma2(w23, xb2, uB2[2 * q + 1]);
                }
            }
            // routing logit l = u . v
            u64t dA2 = 0ull, dB2 = 0ull;
#pragma unroll
            for (int q = 0; q < 8; q++) {
                dA2 = fma2(uA2[q], vA2[q], dA2);
                dB2 = fma2(uB2[q], vB2[q], dB2);
            }
            float a0, a1, b0, b1;
            upk2(dA2, a0, a1); upk2(dB2, b0, b1);
            float lA = a0 + a1, lB = b0 + b1;
            if constexpr (P == 2) {
                lA += g_logits[((size_t)bA * IN_CAPS + i) * NC + n];
                lB += g_logits[((size_t)bB * IN_CAPS + i) * NC + n];
            } else {
                g_logits[((size_t)bA * IN_CAPS + i) * NC + n] = lA;
                g_logits[((size_t)bB * IN_CAPS + i) * NC + n] = lB;
            }
            // softmax over 32 capsules = full-warp reduce
            float mA = lA, mB = lB;
#pragma unroll
            for (int o = 16; o > 0; o >>= 1) {
                mA = fmaxf(mA, __shfl_xor_sync(0xffffffffu, mA, o));
                mB = fmaxf(mB, __shfl_xor_sync(0xffffffffu, mB, o));
            }
            float pA = __expf(lA - mA), pB = __expf(lB - mB);
            float ZA = pA, ZB = pB;
#pragma unroll
            for (int o = 16; o > 0; o >>= 1) {
                ZA += __shfl_xor_sync(0xffffffffu, ZA, o);
                ZB += __shfl_xor_sync(0xffffffffu, ZB, o);
            }
            float cA = pA / ZA, cB = pB / ZB;
            u64t cA2 = pk2(cA, cA), cB2 = pk2(cB, cB);
#pragma unroll
            for (int q = 0; q < 8; q++) {
                accA2[q] = fma2(uA2[q], cA2, accA2[q]);
                accB2[q] = fma2(uB2[q], cB2, accB2[q]);
            }
        }
    }

    // flush partial sums
    float* s = g_s[P];
#pragma unroll
    for (int q = 0; q < 8; q++) {
        float a0, a1, b0, b1;
        upk2(accA2[q], a0, a1); upk2(accB2[q], b0, b1);
        atomicAdd(&s[(bA * NC + n) * OUT_DIM + 2 * q],     a0);
        atomicAdd(&s[(bA * NC + n) * OUT_DIM + 2 * q + 1], a1);
        atomicAdd(&s[(bB * NC + n) * OUT_DIM + 2 * q],     b0);
        atomicAdd(&s[(bB * NC + n) * OUT_DIM + 2 * q + 1], b1);
    }
}

// squash(v) = (|v|^2/(1+|v|^2)/|v|) * v ; pass-0 1/32 scale folded in here
template <int K>
__global__ void squash_kernel(float* out_ext) {
    int idx = blockIdx.x * blockDim.x + threadIdx.x;
    if (idx >= BATCH * NC) return;
    const float scale = (K == 0) ? (1.0f / 32.0f) : 1.0f;
    const float* s = g_s[K];
    float* out;
    if constexpr (K == 2) out = out_ext; else out = g_v[K];

    float w[OUT_DIM];
    float s2 = 0.0f;
#pragma unroll
    for (int e = 0; e < OUT_DIM; e++) {
        w[e] = s[idx * OUT_DIM + e] * scale;
        s2 += w[e] * w[e];
    }
    float sc = s2 / ((1.0f + s2) * sqrtf(fmaxf(s2, 1e-30f)));
#pragma unroll
    for (int e = 0; e < OUT_DIM; e++) out[idx * OUT_DIM + e] = sc * w[e];
}

extern "C" void kernel_launch(void* const* d_in, const int* in_sizes, int n_in,
                              void* d_out, int out_size) {
    const float* x = (const float*)d_in[0];   // [64, 2048, 8]
    const float* W = (const float*)d_in[1];   // [2048, 32, 8, 16]
    float* out = (float*)d_out;               // [64, 32, 16]

    transpose_W<<<IN_CAPS, 256>>>((const float4*)W);
    zero_kernel<<<(3 * NV + 255) / 256, 256>>>();

    dim3 grid(NIB, NBT);                      // 64 x 8 = 512 CTAs of 128 thr
    dim3 sgrid((BATCH * NC + 255) / 256);

    pass_kernel<0><<<grid, 128>>>(x);
    squash_kernel<0><<<sgrid, 256>>>(nullptr);

    pass_kernel<1><<<grid, 128>>>(x);
    squash_kernel<1><<<sgrid, 256>>>(nullptr);

    pass_kernel<2><<<grid, 128>>>(x);
    squash_kernel<2><<<sgrid, 256>>>(out);
}

// round 6
// speedup vs baseline: 1.8314x; 1.1247x over previous
#include <cuda_runtime.h>
#include <math.h>

// Problem constants
#define BATCH    64
#define IN_CAPS  2048
#define IN_DIM   8
#define NC       32
#define OUT_DIM  16
#define IBLK     32                      // input capsules per CTA
#define NIB      (IN_CAPS / IBLK)        // 64
#define BTILE    8                       // batch rows per CTA (4 warps x 2 rows)
#define NBT      (BATCH / BTILE)         // 8
#define NV       (BATCH * NC * OUT_DIM)  // 32768

typedef unsigned long long u64t;

// Scratch (static device globals — no allocation allowed)
__device__ __align__(16) float  g_s[3][NV];
__device__ __align__(16) float  g_v[2][NV];
__device__ float g_logits[(size_t)BATCH * IN_CAPS * NC];          // 16MB
// Transposed weights: W_t[i][d][e/4][n] as float4  (32MB, L2-resident)
__device__ __align__(16) float4 g_Wt4[(size_t)IN_CAPS * IN_DIM * 4 * NC];

// ---- packed f32x2 helpers (Blackwell FFMA2, PTX-only) ----
__device__ __forceinline__ u64t pk2(float lo, float hi) {
    u64t r; asm("mov.b64 %0,{%1,%2};" : "=l"(r) : "f"(lo), "f"(hi)); return r;
}
__device__ __forceinline__ void upk2(u64t v, float& lo, float& hi) {
    asm("mov.b64 {%0,%1},%2;" : "=f"(lo), "=f"(hi) : "l"(v));
}
__device__ __forceinline__ u64t fma2(u64t a, u64t b, u64t c) {
    u64t d; asm("fma.rn.f32x2 %0,%1,%2,%3;" : "=l"(d) : "l"(a), "l"(b), "l"(c)); return d;
}
// packed fire-and-forget global reduction
__device__ __forceinline__ void red_add_v2(float* addr, float a, float b) {
    asm volatile("red.global.add.v2.f32 [%0], {%1,%2};" :: "l"(addr), "f"(a), "f"(b) : "memory");
}

// W[i][n][d][e] (row-major) -> W_t[i][d*4+q][n] float4 (q = e/4)
// Also zero-initializes the g_s accumulators.
__global__ void __launch_bounds__(256)
transpose_W(const float4* __restrict__ W4) {
    __shared__ float4 t[32][33];
    const int i   = blockIdx.x;
    const int tid = threadIdx.x;
    if (i < 48) {  // 48 blocks x 256 thr x 8 floats = 98304 >= 3*NV
        int base = (i * 256 + tid) * 8;
#pragma unroll
        for (int k = 0; k < 8; k++)
            if (base + k < 3 * NV) ((float*)g_s)[base + k] = 0.0f;
    }
    const float4* src = W4 + (size_t)i * 1024;     // 1024 float4 per capsule
#pragma unroll
    for (int k = 0; k < 4; k++) {
        int idx = tid + 256 * k;                   // in-linear = n*32 + dq
        t[idx >> 5][idx & 31] = src[idx];
    }
    __syncthreads();
    float4* dst = g_Wt4 + (size_t)i * 1024;
#pragma unroll
    for (int k = 0; k < 4; k++) {
        int idx = tid + 256 * k;                   // out-linear = dq*32 + n
        dst[idx] = t[idx & 31][idx >> 5];
    }
}

// P = routing pass (0,1,2). lane = capsule n; warp g owns 2 batch rows.
// No shared memory, no barriers: W streamed per-lane through L1 (coalesced).
template <int P>
__global__ void __launch_bounds__(128, 4)
pass_kernel(const float* __restrict__ x) {
    const int tid = threadIdx.x;
    const int n   = tid & 31;
    const int g   = tid >> 5;                  // warp 0..3
    const int bA  = blockIdx.y * BTILE + g * 2;
    const int bB  = bA + 1;
    const int i0  = blockIdx.x * IBLK;

    u64t accA2[8], accB2[8];
#pragma unroll
    for (int q = 0; q < 8; q++) { accA2[q] = 0ull; accB2[q] = 0ull; }

    u64t vA2[8], vB2[8];
    if constexpr (P > 0) {
        const float4* va = (const float4*)&g_v[P - 1][(bA * NC + n) * OUT_DIM];
        const float4* vb = (const float4*)&g_v[P - 1][(bB * NC + n) * OUT_DIM];
#pragma unroll
        for (int q = 0; q < 4; q++) {
            float4 a = va[q], b = vb[q];
            vA2[2 * q] = pk2(a.x, a.y); vA2[2 * q + 1] = pk2(a.z, a.w);
            vB2[2 * q] = pk2(b.x, b.y); vB2[2 * q + 1] = pk2(b.z, b.w);
        }
    }

#pragma unroll 2
    for (int ii = 0; ii < IBLK; ii++) {
        const int i = i0 + ii;

        // P=2: prior logits — issue first so the load overlaps u-compute
        float lA0 = 0.0f, lB0 = 0.0f;
        if constexpr (P == 2) {
            lA0 = __ldg(&g_logits[((size_t)bA * IN_CAPS + i) * NC + n]);
            lB0 = __ldg(&g_logits[((size_t)bB * IN_CAPS + i) * NC + n]);
        }

        // x rows: same address warp-wide -> broadcast loads
        const float4* xrA = (const float4*)(x + ((size_t)bA * IN_CAPS + i) * IN_DIM);
        const float4* xrB = (const float4*)(x + ((size_t)bB * IN_CAPS + i) * IN_DIM);
        float4 xa0 = __ldg(xrA), xa1 = __ldg(xrA + 1);
        float4 xb0 = __ldg(xrB), xb1 = __ldg(xrB + 1);
        float xsA[8] = {xa0.x, xa0.y, xa0.z, xa0.w, xa1.x, xa1.y, xa1.z, xa1.w};
        float xsB[8] = {xb0.x, xb0.y, xb0.z, xb0.w, xb1.x, xb1.y, xb1.z, xb1.w};

        const float4* wp = g_Wt4 + (size_t)i * 1024 + n;   // + (d*4+q)*32 per term

        if constexpr (P == 0) {
            // c = 1/32 uniformly (softmax of zeros): accumulate raw sums
#pragma unroll
            for (int d = 0; d < IN_DIM; d++) {
                u64t xa2 = pk2(xsA[d], xsA[d]);
                u64t xb2 = pk2(xsB[d], xsB[d]);
#pragma unroll
                for (int q = 0; q < 4; q++) {
                    float4 w = __ldg(wp + (d * 4 + q) * 32);
                    u64t w01 = pk2(w.x, w.y), w23 = pk2(w.z, w.w);
                    accA2[2 * q]     = fma2(w01, xa2, accA2[2 * q]);
                    accA2[2 * q + 1] = fma2(w23, xa2, accA2[2 * q + 1]);
                    accB2[2 * q]     = fma2(w01, xb2, accB2[2 * q]);
                    accB2[2 * q + 1] = fma2(w23, xb2, accB2[2 * q + 1]);
                }
            }
        } else {
            u64t uA2[8], uB2[8];
#pragma unroll
            for (int q = 0; q < 8; q++) { uA2[q] = 0ull; uB2[q] = 0ull; }
#pragma unroll
            for (int d = 0; d < IN_DIM; d++) {
                u64t xa2 = pk2(xsA[d], xsA[d]);
                u64t xb2 = pk2(xsB[d], xsB[d]);
#pragma unroll
                for (int q = 0; q < 4; q++) {
                    float4 w = __ldg(wp + (d * 4 + q) * 32);
                    u64t w01 = pk2(w.x, w.y), w23 = pk2(w.z, w.w);
                    uA2[2 * q]     = fma2(w01, xa2, uA2[2 * q]);
                    uA2[2 * q + 1] = fma2(w23, xa2, uA2[2 * q + 1]);
                    uB2[2 * q]     = fma2(w01, xb2, uB2[2 * q]);
                    uB2[2 * q + 1] = fma2(w23, xb2, uB2[2 * q + 1]);
                }
            }
            // routing logit l = u . v
            u64t dA2 = 0ull, dB2 = 0ull;
#pragma unroll
            for (int q = 0; q < 8; q++) {
                dA2 = fma2(uA2[q], vA2[q], dA2);
                dB2 = fma2(uB2[q], vB2[q], dB2);
            }
            float a0, a1, b0, b1;
            upk2(dA2, a0, a1); upk2(dB2, b0, b1);
            float lA = a0 + a1 + lA0, lB = b0 + b1 + lB0;
            if constexpr (P == 1) {
                g_logits[((size_t)bA * IN_CAPS + i) * NC + n] = lA;
                g_logits[((size_t)bB * IN_CAPS + i) * NC + n] = lB;
            }
            // softmax over 32 capsules WITHOUT max subtraction:
            // logits are bounded (|l| << 88) so exp cannot overflow; this is
            // mathematically identical to the max-subtracted softmax.
            float pA = __expf(lA), pB = __expf(lB);
            float ZA = pA, ZB = pB;
#pragma unroll
            for (int o = 16; o > 0; o >>= 1) {       // two trees interleave -> ILP
                ZA += __shfl_xor_sync(0xffffffffu, ZA, o);
                ZB += __shfl_xor_sync(0xffffffffu, ZB, o);
            }
            float cA = __fdividef(pA, ZA), cB = __fdividef(pB, ZB);
            u64t cA2 = pk2(cA, cA), cB2 = pk2(cB, cB);
#pragma unroll
            for (int q = 0; q < 8; q++) {
                accA2[q] = fma2(uA2[q], cA2, accA2[q]);
                accB2[q] = fma2(uB2[q], cB2, accB2[q]);
            }
        }
    }

    // flush partial sums (packed vector red, no return value)
    float* s = g_s[P];
#pragma unroll
    for (int q = 0; q < 8; q++) {
        float a0, a1, b0, b1;
        upk2(accA2[q], a0, a1); upk2(accB2[q], b0, b1);
        red_add_v2(&s[(bA * NC + n) * OUT_DIM + 2 * q], a0, a1);
        red_add_v2(&s[(bB * NC + n) * OUT_DIM + 2 * q], b0, b1);
    }
}

// squash(v) = (|v|^2/(1+|v|^2)/|v|) * v ; pass-0 1/32 scale folded in here
template <int K>
__global__ void squash_kernel(float* out_ext) {
    int idx = blockIdx.x * blockDim.x + threadIdx.x;
    if (idx >= BATCH * NC) return;
    const float scale = (K == 0) ? (1.0f / 32.0f) : 1.0f;
    const float* s = g_s[K];
    float* out;
    if constexpr (K == 2) out = out_ext; else out = g_v[K];

    float w[OUT_DIM];
    float s2 = 0.0f;
#pragma unroll
    for (int e = 0; e < OUT_DIM; e++) {
        w[e] = s[idx * OUT_DIM + e] * scale;
        s2 += w[e] * w[e];
    }
    float sc = s2 / ((1.0f + s2) * sqrtf(fmaxf(s2, 1e-30f)));
#pragma unroll
    for (int e = 0; e < OUT_DIM; e++) out[idx * OUT_DIM + e] = sc * w[e];
}

extern "C" void kernel_launch(void* const* d_in, const int* in_sizes, int n_in,
                              void* d_out, int out_size) {
    const float* x = (const float*)d_in[0];   // [64, 2048, 8]
    const float* W = (const float*)d_in[1];   // [2048, 32, 8, 16]
    float* out = (float*)d_out;               // [64, 32, 16]

    transpose_W<<<IN_CAPS, 256>>>((const float4*)W);   // also zeroes g_s

    dim3 grid(NIB, NBT);                      // 64 x 8 = 512 CTAs of 128 thr
    dim3 sgrid((BATCH * NC + 255) / 256);

    pass_kernel<0><<<grid, 128>>>(x);
    squash_kernel<0><<<sgrid, 256>>>(nullptr);

    pass_kernel<1><<<grid, 128>>>(x);
    squash_kernel<1><<<sgrid, 256>>>(nullptr);

    pass_kernel<2><<<grid, 128>>>(x);
    squash_kernel<2><<<sgrid, 256>>>(out);
}

// round 7
// speedup vs baseline: 1.8764x; 1.0246x over previous
#include <cuda_runtime.h>
#include <math.h>

// Problem constants
#define BATCH    64
#define IN_CAPS  2048
#define IN_DIM   8
#define NC       32
#define OUT_DIM  16
#define IBLK     32                      // input capsules per CTA
#define NIB      (IN_CAPS / IBLK)        // 64
#define BTILE    8                       // batch rows per CTA (4 warps x 2 rows)
#define NBT      (BATCH / BTILE)         // 8
#define NV       (BATCH * NC * OUT_DIM)  // 32768

typedef unsigned long long u64t;

// Scratch (static device globals — no allocation allowed)
__device__ __align__(16) float  g_s[3][NV];
__device__ __align__(16) float  g_v[2][NV];
__device__ float g_logits[(size_t)BATCH * IN_CAPS * NC];          // 16MB
// Transposed weights: W_t[i][d][e/4][n] as float4  (32MB, L2-resident)
__device__ __align__(16) float4 g_Wt4[(size_t)IN_CAPS * IN_DIM * 4 * NC];

// ---- packed f32x2 helpers (Blackwell FFMA2, PTX-only) ----
__device__ __forceinline__ u64t pk2(float lo, float hi) {
    u64t r; asm("mov.b64 %0,{%1,%2};" : "=l"(r) : "f"(lo), "f"(hi)); return r;
}
__device__ __forceinline__ void upk2(u64t v, float& lo, float& hi) {
    asm("mov.b64 {%0,%1},%2;" : "=f"(lo), "=f"(hi) : "l"(v));
}
__device__ __forceinline__ u64t fma2(u64t a, u64t b, u64t c) {
    u64t d; asm("fma.rn.f32x2 %0,%1,%2,%3;" : "=l"(d) : "l"(a), "l"(b), "l"(c)); return d;
}
__device__ __forceinline__ u64t add2(u64t a, u64t b) {
    u64t d; asm("add.rn.f32x2 %0,%1,%2;" : "=l"(d) : "l"(a), "l"(b)); return d;
}
// packed fire-and-forget global reduction
__device__ __forceinline__ void red_add_v2(float* addr, float a, float b) {
    asm volatile("red.global.add.v2.f32 [%0], {%1,%2};" :: "l"(addr), "f"(a), "f"(b) : "memory");
}

// W[i][n][d][e] (row-major) -> W_t[i][d*4+q][n] float4 (q = e/4)
// Also zero-initializes the g_s accumulators.
__global__ void __launch_bounds__(256)
transpose_W(const float4* __restrict__ W4) {
    __shared__ float4 t[32][33];
    const int i   = blockIdx.x;
    const int tid = threadIdx.x;
    if (i < 48) {  // 48 blocks x 256 thr x 8 floats = 98304 >= 3*NV
        int base = (i * 256 + tid) * 8;
#pragma unroll
        for (int k = 0; k < 8; k++)
            if (base + k < 3 * NV) ((float*)g_s)[base + k] = 0.0f;
    }
    const float4* src = W4 + (size_t)i * 1024;     // 1024 float4 per capsule
#pragma unroll
    for (int k = 0; k < 4; k++) {
        int idx = tid + 256 * k;                   // in-linear = n*32 + dq
        t[idx >> 5][idx & 31] = src[idx];
    }
    __syncthreads();
    float4* dst = g_Wt4 + (size_t)i * 1024;
#pragma unroll
    for (int k = 0; k < 4; k++) {
        int idx = tid + 256 * k;                   // out-linear = dq*32 + n
        dst[idx] = t[idx & 31][idx >> 5];
    }
}

// P = routing pass (0,1,2). lane = capsule n; warp g owns 2 batch rows.
// v lives in smem (lane-consecutive u64 -> conflict-free LDS.64).
template <int P>
__global__ void __launch_bounds__(128, 5)
pass_kernel(const float* __restrict__ x) {
    // vs[warp][row(A/B)][q][n] : 4*2*8*32 u64 = 16KB
    __shared__ u64t vs[4][2][8][32];

    const int tid = threadIdx.x;
    const int n   = tid & 31;
    const int g   = tid >> 5;                  // warp 0..3
    const int bA  = blockIdx.y * BTILE + g * 2;
    const int bB  = bA + 1;
    const int i0  = blockIdx.x * IBLK;

    u64t accA2[8], accB2[8];
#pragma unroll
    for (int q = 0; q < 8; q++) { accA2[q] = 0ull; accB2[q] = 0ull; }

    if constexpr (P > 0) {
        const float4* va = (const float4*)&g_v[P - 1][(bA * NC + n) * OUT_DIM];
        const float4* vb = (const float4*)&g_v[P - 1][(bB * NC + n) * OUT_DIM];
#pragma unroll
        for (int q = 0; q < 4; q++) {
            float4 a = va[q], b = vb[q];
            vs[g][0][2 * q][n]     = pk2(a.x, a.y);
            vs[g][0][2 * q + 1][n] = pk2(a.z, a.w);
            vs[g][1][2 * q][n]     = pk2(b.x, b.y);
            vs[g][1][2 * q + 1][n] = pk2(b.z, b.w);
        }
        __syncwarp();   // each warp only reads its own slice
    }

    for (int ii = 0; ii < IBLK; ii++) {
        const int i = i0 + ii;

        // P=2: prior logits — issue first so the load overlaps u-compute
        float lA0 = 0.0f, lB0 = 0.0f;
        if constexpr (P == 2) {
            lA0 = __ldg(&g_logits[((size_t)bA * IN_CAPS + i) * NC + n]);
            lB0 = __ldg(&g_logits[((size_t)bB * IN_CAPS + i) * NC + n]);
        }

        // x rows: same address warp-wide -> broadcast loads
        const float4* xrA = (const float4*)(x + ((size_t)bA * IN_CAPS + i) * IN_DIM);
        const float4* xrB = (const float4*)(x + ((size_t)bB * IN_CAPS + i) * IN_DIM);
        float4 xa0 = __ldg(xrA), xa1 = __ldg(xrA + 1);
        float4 xb0 = __ldg(xrB), xb1 = __ldg(xrB + 1);
        float xsA[8] = {xa0.x, xa0.y, xa0.z, xa0.w, xa1.x, xa1.y, xa1.z, xa1.w};
        float xsB[8] = {xb0.x, xb0.y, xb0.z, xb0.w, xb1.x, xb1.y, xb1.z, xb1.w};

        const float4* wp = g_Wt4 + (size_t)i * 1024 + n;   // + (d*4+q)*32 per term

        if constexpr (P == 0) {
            // c = 1/32 uniformly (softmax of zeros): accumulate raw sums
#pragma unroll
            for (int d = 0; d < IN_DIM; d++) {
                u64t xa2 = pk2(xsA[d], xsA[d]);
                u64t xb2 = pk2(xsB[d], xsB[d]);
#pragma unroll
                for (int q = 0; q < 4; q++) {
                    float4 w = __ldg(wp + (d * 4 + q) * 32);
                    u64t w01 = pk2(w.x, w.y), w23 = pk2(w.z, w.w);
                    accA2[2 * q]     = fma2(w01, xa2, accA2[2 * q]);
                    accA2[2 * q + 1] = fma2(w23, xa2, accA2[2 * q + 1]);
                    accB2[2 * q]     = fma2(w01, xb2, accB2[2 * q]);
                    accB2[2 * q + 1] = fma2(w23, xb2, accB2[2 * q + 1]);
                }
            }
        } else {
            u64t uA2[8], uB2[8];
#pragma unroll
            for (int q = 0; q < 8; q++) { uA2[q] = 0ull; uB2[q] = 0ull; }
#pragma unroll
            for (int d = 0; d < IN_DIM; d++) {
                u64t xa2 = pk2(xsA[d], xsA[d]);
                u64t xb2 = pk2(xsB[d], xsB[d]);
#pragma unroll
                for (int q = 0; q < 4; q++) {
                    float4 w = __ldg(wp + (d * 4 + q) * 32);
                    u64t w01 = pk2(w.x, w.y), w23 = pk2(w.z, w.w);
                    uA2[2 * q]     = fma2(w01, xa2, uA2[2 * q]);
                    uA2[2 * q + 1] = fma2(w23, xa2, uA2[2 * q + 1]);
                    uB2[2 * q]     = fma2(w01, xb2, uB2[2 * q]);
                    uB2[2 * q + 1] = fma2(w23, xb2, uB2[2 * q + 1]);
                }
            }
            // routing logit l = u . v  (v from smem, 2 chains for ILP)
            u64t dA0 = 0ull, dA1 = 0ull, dB0 = 0ull, dB1 = 0ull;
#pragma unroll
            for (int q = 0; q < 8; q += 2) {
                dA0 = fma2(uA2[q],     vs[g][0][q][n],     dA0);
                dA1 = fma2(uA2[q + 1], vs[g][0][q + 1][n], dA1);
                dB0 = fma2(uB2[q],     vs[g][1][q][n],     dB0);
                dB1 = fma2(uB2[q + 1], vs[g][1][q + 1][n], dB1);
            }
            u64t dA2 = add2(dA0, dA1), dB2 = add2(dB0, dB1);
            float a0, a1, b0, b1;
            upk2(dA2, a0, a1); upk2(dB2, b0, b1);
            float lA = a0 + a1 + lA0, lB = b0 + b1 + lB0;
            if constexpr (P == 1) {
                g_logits[((size_t)bA * IN_CAPS + i) * NC + n] = lA;
                g_logits[((size_t)bB * IN_CAPS + i) * NC + n] = lB;
            }
            // softmax over 32 capsules WITHOUT max subtraction:
            // logits are bounded (|l| << 88), so exp cannot overflow.
            float pA = __expf(lA), pB = __expf(lB);
            float ZA = pA, ZB = pB;
#pragma unroll
            for (int o = 16; o > 0; o >>= 1) {       // two trees interleave -> ILP
                ZA += __shfl_xor_sync(0xffffffffu, ZA, o);
                ZB += __shfl_xor_sync(0xffffffffu, ZB, o);
            }
            float cA = __fdividef(pA, ZA), cB = __fdividef(pB, ZB);
            u64t cA2 = pk2(cA, cA), cB2 = pk2(cB, cB);
#pragma unroll
            for (int q = 0; q < 8; q++) {
                accA2[q] = fma2(uA2[q], cA2, accA2[q]);
                accB2[q] = fma2(uB2[q], cB2, accB2[q]);
            }
        }
    }

    // flush partial sums (packed vector red, no return value)
    float* s = g_s[P];
#pragma unroll
    for (int q = 0; q < 8; q++) {
        float a0, a1, b0, b1;
        upk2(accA2[q], a0, a1); upk2(accB2[q], b0, b1);
        red_add_v2(&s[(bA * NC + n) * OUT_DIM + 2 * q], a0, a1);
        red_add_v2(&s[(bB * NC + n) * OUT_DIM + 2 * q], b0, b1);
    }
}

// squash(v) = (|v|^2/(1+|v|^2)/|v|) * v ; pass-0 1/32 scale folded in here
template <int K>
__global__ void squash_kernel(float* out_ext) {
    int idx = blockIdx.x * blockDim.x + threadIdx.x;
    if (idx >= BATCH * NC) return;
    const float scale = (K == 0) ? (1.0f / 32.0f) : 1.0f;
    const float* s = g_s[K];
    float* out;
    if constexpr (K == 2) out = out_ext; else out = g_v[K];

    float w[OUT_DIM];
    float s2 = 0.0f;
#pragma unroll
    for (int e = 0; e < OUT_DIM; e++) {
        w[e] = s[idx * OUT_DIM + e] * scale;
        s2 += w[e] * w[e];
    }
    float sc = s2 / ((1.0f + s2) * sqrtf(fmaxf(s2, 1e-30f)));
#pragma unroll
    for (int e = 0; e < OUT_DIM; e++) out[idx * OUT_DIM + e] = sc * w[e];
}

extern "C" void kernel_launch(void* const* d_in, const int* in_sizes, int n_in,
                              void* d_out, int out_size) {
    const float* x = (const float*)d_in[0];   // [64, 2048, 8]
    const float* W = (const float*)d_in[1];   // [2048, 32, 8, 16]
    float* out = (float*)d_out;               // [64, 32, 16]

    transpose_W<<<IN_CAPS, 256>>>((const float4*)W);   // also zeroes g_s

    dim3 grid(NIB, NBT);                      // 64 x 8 = 512 CTAs of 128 thr
    dim3 sgrid((BATCH * NC + 255) / 256);

    pass_kernel<0><<<grid, 128>>>(x);
    squash_kernel<0><<<sgrid, 256>>>(nullptr);

    pass_kernel<1><<<grid, 128>>>(x);
    squash_kernel<1><<<sgrid, 256>>>(nullptr);

    pass_kernel<2><<<grid, 128>>>(x);
    squash_kernel<2><<<sgrid, 256>>>(out);
}